// round 1
// baseline (speedup 1.0000x reference)
#include <cuda_runtime.h>
#include <cuda_bf16.h>
#include <math.h>

// ---------------------------------------------------------------------------
// SupConLossWithPrototype: M=8192 samples, K=128 dim, B=100 prototypes.
// Restructured:
//   novel[i]  = !(labels[i] in proto_labels)
//   Fn        = compacted novel feature rows (Nn x 128)
//   E[i]      = sum_{j novel} exp(f_i . Fn_j / T)      <-- only O(M^2 K) term
//   sum_S row = factorized via g = sum_{j novel} f_j
//   loss assembled per-row, reduced deterministically.
// ---------------------------------------------------------------------------

#define MAXM 8192
#define NCHUNK 8

__device__ float d_Fn[(size_t)MAXM * 128];
__device__ int   d_pos[MAXM];
__device__ int   d_flag[MAXM];          // 1 = novel
__device__ int   d_Nn;
__device__ float d_gpart[64 * 128];
__device__ float d_g[128];
__device__ float d_Epart[(size_t)NCHUNK * MAXM];
__device__ float d_rowloss[MAXM];

// Fast exp on the FMA/ALU pipes (no MUFU). Valid for |x| < ~80.
// exp(x) = 2^(x*log2e); round via magic constant; degree-6 poly for 2^r,
// r in [-0.5,0.5]; scale by adding k to the exponent bits. rel err ~1.5e-7.
__device__ __forceinline__ float fexp(float x) {
    float t = x * 1.4426950408889634f;
    float z = t + 12582912.0f;                 // 1.5 * 2^23
    int   ki = __float_as_int(z) - 0x4B400000; // round(t)
    float r = t - (z - 12582912.0f);
    float p =            1.5403530393381610e-4f;
    p = fmaf(p, r,       1.3333558146428443e-3f);
    p = fmaf(p, r,       9.6181291076284772e-3f);
    p = fmaf(p, r,       5.5504108664821580e-2f);
    p = fmaf(p, r,       2.4022650695910072e-1f);
    p = fmaf(p, r,       6.9314718055994531e-1f);
    p = fmaf(p, r,       1.0f);
    return __int_as_float(__float_as_int(p) + (ki << 23));
}

// --------------------------- setup kernels --------------------------------

__global__ void flags_kernel(const int* __restrict__ labels,
                             const int* __restrict__ plab, int M, int B) {
    __shared__ int sPL[256];
    int tid = threadIdx.x;
    if (tid < B) sPL[tid] = plab[tid];
    __syncthreads();
    int i = blockIdx.x * 256 + tid;
    if (i < M) {
        int lab = labels[i];
        int hit = 0;
        for (int b = 0; b < B; ++b) hit |= (lab == sPL[b]);
        d_flag[i] = hit ^ 1;
    }
}

// Single-block exclusive scan of novel flags -> compaction positions + Nn.
__global__ void scan_kernel(int M) {
    __shared__ int sWarp[32];
    __shared__ int sBase;
    __shared__ int sTot;
    int tid = threadIdx.x;
    int lane = tid & 31, wid = tid >> 5;
    if (tid == 0) sBase = 0;
    __syncthreads();
    for (int c0 = 0; c0 < M; c0 += 1024) {
        int i = c0 + tid;
        int f = (i < M) ? d_flag[i] : 0;
        unsigned bal = __ballot_sync(0xffffffffu, f != 0);
        int lanePre = __popc(bal & ((1u << lane) - 1u));
        if (lane == 0) sWarp[wid] = __popc(bal);
        __syncthreads();
        if (wid == 0) {
            int v = sWarp[lane];
            int pre = v;
            #pragma unroll
            for (int off = 1; off < 32; off <<= 1) {
                int n = __shfl_up_sync(0xffffffffu, pre, off);
                if (lane >= off) pre += n;
            }
            sWarp[lane] = pre - v;          // exclusive within chunk
            if (lane == 31) sTot = pre;     // chunk total
        }
        __syncthreads();
        if (i < M && f) d_pos[i] = sBase + sWarp[wid] + lanePre;
        __syncthreads();
        if (tid == 0) sBase += sTot;
        __syncthreads();
    }
    if (tid == 0) d_Nn = sBase;
}

// Partial sums of novel feature rows (deterministic two-stage).
__global__ void gpart_kernel(const float* __restrict__ F, int M) {
    int k = threadIdx.x;                 // 128 threads
    int r0 = blockIdx.x * 128;
    int r1 = min(r0 + 128, M);
    float s = 0.f;
    for (int r = r0; r < r1; ++r)
        if (d_flag[r]) s += F[(size_t)r * 128 + k];
    d_gpart[blockIdx.x * 128 + k] = s;
}

__global__ void gred_kernel(int nb) {
    int k = threadIdx.x;
    float s = 0.f;
    for (int b = 0; b < nb; ++b) s += d_gpart[b * 128 + k];
    d_g[k] = s;
}

// Compact novel rows into contiguous Fn (one warp per row, float4 copies).
__global__ void compact_kernel(const float* __restrict__ F, int M) {
    int gt = blockIdx.x * blockDim.x + threadIdx.x;
    int lane = gt & 31, gw = gt >> 5;
    int nw = (gridDim.x * blockDim.x) >> 5;
    for (int r = gw; r < M; r += nw) {
        if (d_flag[r]) {
            int p = d_pos[r];
            float4 v = *(const float4*)(F + (size_t)r * 128 + lane * 4);
            *(float4*)(d_Fn + (size_t)p * 128 + lane * 4) = v;
        }
    }
}

// --------------------- main exp-sum GEMM-like kernel -----------------------
// Block: 128 rows x 128 novel cols per tile, 256 threads, 8x8 microtile.
// smem: sA[k][i] 64KB + sB[k][j] 32KB (K split in two 64-halves) = 96KB
// -> 2 blocks/SM. Exp computed with fexp on the FMA pipe, accumulated per row.

__global__ __launch_bounds__(256, 2)
void expsum_kernel(const float* __restrict__ F, int M) {
    extern __shared__ float smem[];
    float (*sA)[128] = (float (*)[128])smem;              // [128][128]
    float (*sB)[128] = (float (*)[128])(smem + 128 * 128); // [64][128]

    int tid = threadIdx.x;
    int tx = tid & 15, ty = tid >> 4;
    int rowbase = blockIdx.x * 128;
    int chunk = blockIdx.y;

    // Load A tile transposed: sA[k][i] = F[rowbase+i][k]
    {
        int r = tid >> 1, h = tid & 1;
        const float* src = F + (size_t)(rowbase + r) * 128 + h * 64;
        #pragma unroll
        for (int q = 0; q < 16; ++q) {
            float4 v = *(const float4*)(src + q * 4);
            int k = h * 64 + q * 4;
            sA[k + 0][r] = v.x; sA[k + 1][r] = v.y;
            sA[k + 2][r] = v.z; sA[k + 3][r] = v.w;
        }
    }

    int Nn = d_Nn;
    int ntiles = (Nn + 127) >> 7;

    float rowsum[8];
    #pragma unroll
    for (int r = 0; r < 8; ++r) rowsum[r] = 0.f;

    for (int t = chunk; t < ntiles; t += NCHUNK) {
        float acc[8][8];
        #pragma unroll
        for (int r = 0; r < 8; ++r)
            #pragma unroll
            for (int c = 0; c < 8; ++c) acc[r][c] = 0.f;

        #pragma unroll
        for (int kk = 0; kk < 2; ++kk) {
            __syncthreads();
            // Load B half-tile transposed, zero-fill past Nn
            {
                int j = tid >> 1, kh = tid & 1;
                int gj = t * 128 + j;
                const float* src = d_Fn + (size_t)gj * 128 + kk * 64 + kh * 32;
                bool val = (gj < Nn);
                #pragma unroll
                for (int q = 0; q < 8; ++q) {
                    float4 v = val ? *(const float4*)(src + q * 4)
                                   : make_float4(0.f, 0.f, 0.f, 0.f);
                    int k = kh * 32 + q * 4;
                    sB[k + 0][j] = v.x; sB[k + 1][j] = v.y;
                    sB[k + 2][j] = v.z; sB[k + 3][j] = v.w;
                }
            }
            __syncthreads();

            #pragma unroll 8
            for (int k = 0; k < 64; ++k) {
                float4 a0 = *(const float4*)&sA[kk * 64 + k][ty * 8];
                float4 a1 = *(const float4*)&sA[kk * 64 + k][ty * 8 + 4];
                float4 b0 = *(const float4*)&sB[k][tx * 8];
                float4 b1 = *(const float4*)&sB[k][tx * 8 + 4];
                float a[8] = {a0.x, a0.y, a0.z, a0.w, a1.x, a1.y, a1.z, a1.w};
                float b[8] = {b0.x, b0.y, b0.z, b0.w, b1.x, b1.y, b1.z, b1.w};
                #pragma unroll
                for (int r = 0; r < 8; ++r)
                    #pragma unroll
                    for (int c = 0; c < 8; ++c)
                        acc[r][c] = fmaf(a[r], b[c], acc[r][c]);
            }
        }

        // exp + per-row accumulate (mask invalid tail columns)
        #pragma unroll
        for (int c = 0; c < 8; ++c) {
            int gj = t * 128 + tx * 8 + c;
            if (gj < Nn) {
                #pragma unroll
                for (int r = 0; r < 8; ++r)
                    rowsum[r] += fexp(acc[r][c] * 5.0f);
            }
        }
    }

    // Reduce 16 tx-partials per row, write per-chunk partial (deterministic).
    __syncthreads();
    float* sred = &sA[0][0];
    #pragma unroll
    for (int r = 0; r < 8; ++r)
        sred[(ty * 8 + r) * 16 + tx] = rowsum[r];
    __syncthreads();
    if (tid < 128) {
        float s = 0.f;
        #pragma unroll
        for (int x = 0; x < 16; ++x) s += sred[tid * 16 + x];
        d_Epart[(size_t)chunk * M + rowbase + tid] = s;
    }
}

// --------------------------- finalize per row ------------------------------
// One warp per row: proto logits, factorized S-row sum, branch assembly.

__global__ void finalize_kernel(const float* __restrict__ F,
                                const float* __restrict__ protos,
                                const int* __restrict__ labels,
                                int M, int B) {
    extern __shared__ float sP[];        // B * 129 floats (stride 129: no conflicts)
    __shared__ float fR[8][128];
    int tid = threadIdx.x, lane = tid & 31, w = tid >> 5;

    for (int idx = tid; idx < B * 128; idx += 256) {
        int b = idx >> 7, k = idx & 127;
        sP[b * 129 + k] = protos[idx];
    }
    int i = blockIdx.x * 8 + w;
    {
        float4 v = *(const float4*)(F + (size_t)i * 128 + lane * 4);
        *(float4*)&fR[w][lane * 4] = v;
    }
    __syncthreads();

    float dg = 0.f, ds = 0.f;
    #pragma unroll
    for (int q = 0; q < 4; ++q) {
        float fv = fR[w][lane * 4 + q];
        dg = fmaf(fv, d_g[lane * 4 + q], dg);
        ds = fmaf(fv, fv, ds);
    }

    float psum = 0.f, pexp = 0.f, bipi = 0.f;
    int lab = labels[i];
    #pragma unroll
    for (int pb = 0; pb < 4; ++pb) {
        int b = lane + pb * 32;
        if (b < B) {
            float d = 0.f;
            #pragma unroll 8
            for (int k = 0; k < 128; ++k)
                d = fmaf(fR[w][k], sP[b * 129 + k], d);
            float P = d * 5.0f;
            psum += P;
            pexp += fexp(P);
            if (b == lab) bipi = P;
        }
    }
    #pragma unroll
    for (int off = 16; off; off >>= 1) {
        dg   += __shfl_xor_sync(0xffffffffu, dg, off);
        ds   += __shfl_xor_sync(0xffffffffu, ds, off);
        psum += __shfl_xor_sync(0xffffffffu, psum, off);
        pexp += __shfl_xor_sync(0xffffffffu, pexp, off);
        bipi += __shfl_xor_sync(0xffffffffu, bipi, off);
    }

    if (lane == 0) {
        float E = 0.f;
        #pragma unroll
        for (int c = 0; c < NCHUNK; ++c) E += d_Epart[(size_t)c * M + i];
        float loss;
        if (d_flag[i]) {                       // novel row
            float Sii = ds * 5.0f;
            float den = (E - fexp(Sii)) + psum;
            int cnt = d_Nn - 1;
            if (cnt > 0) {
                float sumS = dg * 5.0f - Sii;  // sum_{j novel, j!=i} S_ij
                loss = -((sumS - logf(den) * (float)cnt) / (float)cnt);
            } else {
                loss = 0.f;
            }
        } else {                               // base row
            loss = -(bipi - logf(E + pexp));
        }
        d_rowloss[i] = loss;
    }
}

__global__ void reduce_kernel(float* __restrict__ out, int M) {
    __shared__ float sm[1024];
    int tid = threadIdx.x;
    float s = 0.f;
    for (int i = tid; i < M; i += 1024) s += d_rowloss[i];
    sm[tid] = s;
    __syncthreads();
    for (int off = 512; off; off >>= 1) {
        if (tid < off) sm[tid] += sm[tid + off];
        __syncthreads();
    }
    if (tid == 0) out[0] = sm[0] / (float)M;
}

// ------------------------------- launcher ----------------------------------

extern "C" void kernel_launch(void* const* d_in, const int* in_sizes, int n_in,
                              void* d_out, int out_size) {
    const float* F      = (const float*)d_in[0];
    const int*   labels = (const int*)d_in[1];
    const float* protos = (const float*)d_in[2];
    const int*   plab   = (const int*)d_in[3];
    int M = in_sizes[1];                  // 8192
    int B = in_sizes[3];                  // 100  (K = in_sizes[2]/B = 128)

    flags_kernel<<<(M + 255) / 256, 256>>>(labels, plab, M, B);
    scan_kernel<<<1, 1024>>>(M);

    int nb = (M + 127) / 128;
    gpart_kernel<<<nb, 128>>>(F, M);
    gred_kernel<<<1, 128>>>(nb);
    compact_kernel<<<128, 256>>>(F, M);

    size_t smemMain = (size_t)(128 * 128 + 64 * 128) * sizeof(float); // 96KB
    cudaFuncSetAttribute(expsum_kernel,
                         cudaFuncAttributeMaxDynamicSharedMemorySize,
                         (int)smemMain);
    expsum_kernel<<<dim3(M / 128, NCHUNK), 256, smemMain>>>(F, M);

    size_t smemP = (size_t)B * 129 * sizeof(float); // ~51.6KB
    cudaFuncSetAttribute(finalize_kernel,
                         cudaFuncAttributeMaxDynamicSharedMemorySize,
                         (int)smemP);
    finalize_kernel<<<M / 8, 256, smemP>>>(F, protos, labels, M, B);

    reduce_kernel<<<1, 1024>>>((float*)d_out, M);
}

// round 3
// speedup vs baseline: 1.8727x; 1.8727x over previous
#include <cuda_runtime.h>
#include <cuda_bf16.h>
#include <math.h>
#include <stdint.h>

// ---------------------------------------------------------------------------
// SupConLossWithPrototype via family-neutral tensor-core path (mma.sync bf16).
//   E[i] = sum_{j novel} exp(f_i . f_j / T), split-bf16 3-pass:
//   hi*hi + hi*lo + lo*hi, fp32 accumulate, fused poly-exp row-reduce.
// ---------------------------------------------------------------------------

#define MAXM 8192
#define NCHUNK 2

__device__ __align__(16) __nv_bfloat16 d_Ahi[(size_t)MAXM * 128];
__device__ __align__(16) __nv_bfloat16 d_Alo[(size_t)MAXM * 128];
__device__ __align__(16) __nv_bfloat16 d_Bhi[(size_t)(MAXM + 128) * 128];
__device__ __align__(16) __nv_bfloat16 d_Blo[(size_t)(MAXM + 128) * 128];
__device__ int   d_pos[MAXM];
__device__ int   d_flag[MAXM];
__device__ int   d_Nn;
__device__ float d_gpart[256 * 128];
__device__ float d_g[128];
__device__ float d_Epart[(size_t)NCHUNK * MAXM];
__device__ float d_rowloss[MAXM];

// ------------------------------ helpers ------------------------------------

__device__ __forceinline__ uint32_t s2u(const void* p) {
    uint32_t a;
    asm("{ .reg .u64 t; cvta.to.shared.u64 t, %1; cvt.u32.u64 %0, t; }"
        : "=r"(a) : "l"(p));
    return a;
}

__device__ __forceinline__ void cp16(uint32_t s, const void* g) {
    asm volatile("cp.async.cg.shared.global [%0], [%1], 16;" :: "r"(s), "l"(g));
}
#define CP_COMMIT() asm volatile("cp.async.commit_group;" ::: "memory")

__device__ __forceinline__ void ldsm4(uint32_t (&r)[4], uint32_t addr) {
    asm volatile("ldmatrix.sync.aligned.m8n8.x4.shared.b16 {%0,%1,%2,%3}, [%4];"
                 : "=r"(r[0]), "=r"(r[1]), "=r"(r[2]), "=r"(r[3]) : "r"(addr));
}

__device__ __forceinline__ void mma16816(float (&d)[4], const uint32_t (&a)[4],
                                         uint32_t b0, uint32_t b1) {
    asm volatile(
        "mma.sync.aligned.m16n8k16.row.col.f32.bf16.bf16.f32 "
        "{%0,%1,%2,%3}, {%4,%5,%6,%7}, {%8,%9}, {%0,%1,%2,%3};"
        : "+f"(d[0]), "+f"(d[1]), "+f"(d[2]), "+f"(d[3])
        : "r"(a[0]), "r"(a[1]), "r"(a[2]), "r"(a[3]), "r"(b0), "r"(b1));
}

// XOR-swizzled smem tile: 128 rows x 256B. chunk' = chunk ^ (row & 7).
__device__ __forceinline__ uint32_t swz(uint32_t base, int row, int kchunk) {
    return base + row * 256 + (((uint32_t)(kchunk ^ (row & 7))) << 4);
}

// exp(5x) on the FMA pipe, rel err ~1.5e-7, |5x| < ~80.
__device__ __forceinline__ float fexp5(float x) {
    const float L = 7.2134752044448170f;      // 5 * log2(e)
    float z = fmaf(x, L, 12582912.0f);
    int   ki = __float_as_int(z) - 0x4B400000;
    float r = fmaf(x, L, 12582912.0f - z);
    float p =      1.5403530393381610e-4f;
    p = fmaf(p, r, 1.3333558146428443e-3f);
    p = fmaf(p, r, 9.6181291076284772e-3f);
    p = fmaf(p, r, 5.5504108664821580e-2f);
    p = fmaf(p, r, 2.4022650695910072e-1f);
    p = fmaf(p, r, 6.9314718055994531e-1f);
    p = fmaf(p, r, 1.0f);
    return __int_as_float(__float_as_int(p) + (ki << 23));
}

__device__ __forceinline__ float fexp(float x) {
    float t = x * 1.4426950408889634f;
    float z = t + 12582912.0f;
    int   ki = __float_as_int(z) - 0x4B400000;
    float r = t - (z - 12582912.0f);
    float p =      1.5403530393381610e-4f;
    p = fmaf(p, r, 1.3333558146428443e-3f);
    p = fmaf(p, r, 9.6181291076284772e-3f);
    p = fmaf(p, r, 5.5504108664821580e-2f);
    p = fmaf(p, r, 2.4022650695910072e-1f);
    p = fmaf(p, r, 6.9314718055994531e-1f);
    p = fmaf(p, r, 1.0f);
    return __int_as_float(__float_as_int(p) + (ki << 23));
}

// --------------------------- setup kernels --------------------------------

__global__ void scan_flags_kernel(const int* __restrict__ labels,
                                  const int* __restrict__ plab, int M, int B) {
    __shared__ int sPL[128];
    __shared__ int sWarp[32];
    __shared__ int sBase, sTot;
    int tid = threadIdx.x, lane = tid & 31, wid = tid >> 5;
    if (tid < B) sPL[tid] = plab[tid];
    if (tid == 0) sBase = 0;
    __syncthreads();
    for (int c0 = 0; c0 < M; c0 += 1024) {
        int i = c0 + tid;
        int f = 0;
        if (i < M) {
            int lab = labels[i];
            int hit = 0;
            for (int b = 0; b < B; ++b) hit |= (lab == sPL[b]);
            f = hit ^ 1;
            d_flag[i] = f;
        }
        unsigned bal = __ballot_sync(0xffffffffu, f != 0);
        int lanePre = __popc(bal & ((1u << lane) - 1u));
        if (lane == 0) sWarp[wid] = __popc(bal);
        __syncthreads();
        if (wid == 0) {
            int v = sWarp[lane];
            int pre = v;
            #pragma unroll
            for (int off = 1; off < 32; off <<= 1) {
                int n = __shfl_up_sync(0xffffffffu, pre, off);
                if (lane >= off) pre += n;
            }
            sWarp[lane] = pre - v;
            if (lane == 31) sTot = pre;
        }
        __syncthreads();
        if (i < M && f) d_pos[i] = sBase + sWarp[wid] + lanePre;
        __syncthreads();
        if (tid == 0) sBase += sTot;
        __syncthreads();
    }
    if (tid == 0) d_Nn = sBase;
}

// Split features into bf16 hi/lo, plain row-major A (all rows) and B
// (compacted novel rows). Tail zeros the pad rows of the last B tile.
__global__ void convert_kernel(const float* __restrict__ F, int M) {
    int idx = blockIdx.x * 256 + threadIdx.x;
    int total = M * 16;
    if (idx < total) {
        int r = idx >> 4, kc = idx & 15;
        float4 v0 = *(const float4*)(F + (size_t)r * 128 + kc * 8);
        float4 v1 = *(const float4*)(F + (size_t)r * 128 + kc * 8 + 4);
        float av[8] = {v0.x, v0.y, v0.z, v0.w, v1.x, v1.y, v1.z, v1.w};
        union { __nv_bfloat16 h[8]; uint4 u; } ph, pl;
        #pragma unroll
        for (int q = 0; q < 8; ++q) {
            __nv_bfloat16 h = __float2bfloat16(av[q]);
            ph.h[q] = h;
            pl.h[q] = __float2bfloat16(av[q] - __bfloat162float(h));
        }
        ((uint4*)d_Ahi)[(size_t)r * 16 + kc] = ph.u;
        ((uint4*)d_Alo)[(size_t)r * 16 + kc] = pl.u;
        if (d_flag[r]) {
            size_t p = (size_t)d_pos[r] * 16 + kc;
            ((uint4*)d_Bhi)[p] = ph.u;
            ((uint4*)d_Blo)[p] = pl.u;
        }
    } else {
        int idx2 = idx - total;
        if (idx2 < 128 * 16) {
            int Nn = d_Nn;
            int pad = ((Nn + 127) & ~127) - Nn;   // rows to zero
            int trow = idx2 >> 4, kc = idx2 & 15;
            if (trow < pad) {
                size_t p = (size_t)(Nn + trow) * 16 + kc;
                uint4 z = make_uint4(0, 0, 0, 0);
                ((uint4*)d_Bhi)[p] = z;
                ((uint4*)d_Blo)[p] = z;
            }
        }
    }
}

__global__ void gpart_kernel(const float* __restrict__ F, int M) {
    int k = threadIdx.x;
    int r0 = blockIdx.x * 32;
    int r1 = min(r0 + 32, M);
    float s = 0.f;
    for (int r = r0; r < r1; ++r)
        if (d_flag[r]) s += F[(size_t)r * 128 + k];
    d_gpart[blockIdx.x * 128 + k] = s;
}

__global__ void gred_kernel(int nb) {
    int k = threadIdx.x;
    float s = 0.f;
    for (int b = 0; b < nb; ++b) s += d_gpart[b * 128 + k];
    d_g[k] = s;
}

// ---------------------- main mma.sync exp-sum kernel -----------------------
// CTA: 128 rows x stream of 128-col novel tiles (stride NCHUNK).
// smem: A hi/lo resident (64KB) + B double buffer hi/lo (128KB) = 192KB.
// 8 warps in 2x4 grid, warp tile 64x32, mma.sync m16n8k16 bf16, 3 passes.

__global__ __launch_bounds__(256, 1) void mma_expsum_kernel(int M) {
    extern __shared__ char dyn[];
    const uint32_t sbase = s2u(dyn);
    const uint32_t sAhi = sbase;
    const uint32_t sAlo = sbase + 32768;
    const uint32_t sBhi[2] = {sbase + 65536, sbase + 131072};
    const uint32_t sBlo[2] = {sbase + 98304, sbase + 163840};

    int tid = threadIdx.x;
    int lane = tid & 31, w = tid >> 5;
    int wr = w >> 2, wc = w & 3;               // warp grid 2 x 4
    int rowbase = blockIdx.x * 128;
    int chunk = blockIdx.y;
    int Nn = d_Nn;
    int ntiles = (Nn + 127) >> 7;
    int nt = (ntiles > chunk) ? ((ntiles - chunk + NCHUNK - 1) / NCHUNK) : 0;

    // Prologue: A hi/lo (group 0, with B0) + B1 (group 1).
    {
        const char* gah = (const char*)d_Ahi + (size_t)blockIdx.x * 32768;
        const char* gal = (const char*)d_Alo + (size_t)blockIdx.x * 32768;
        #pragma unroll
        for (int it = 0; it < 8; ++it) {
            int c = it * 256 + tid;            // 2048 chunks per tile image
            int row = c >> 4, kc = c & 15;
            cp16(swz(sAhi, row, kc), gah + (size_t)c * 16);
            cp16(swz(sAlo, row, kc), gal + (size_t)c * 16);
        }
        if (nt > 0) {
            const char* gbh = (const char*)d_Bhi + (size_t)chunk * 32768;
            const char* gbl = (const char*)d_Blo + (size_t)chunk * 32768;
            #pragma unroll
            for (int it = 0; it < 8; ++it) {
                int c = it * 256 + tid;
                int row = c >> 4, kc = c & 15;
                cp16(swz(sBhi[0], row, kc), gbh + (size_t)c * 16);
                cp16(swz(sBlo[0], row, kc), gbl + (size_t)c * 16);
            }
        }
        CP_COMMIT();
        if (nt > 1) {
            int t1 = chunk + NCHUNK;
            const char* gbh = (const char*)d_Bhi + (size_t)t1 * 32768;
            const char* gbl = (const char*)d_Blo + (size_t)t1 * 32768;
            #pragma unroll
            for (int it = 0; it < 8; ++it) {
                int c = it * 256 + tid;
                int row = c >> 4, kc = c & 15;
                cp16(swz(sBhi[1], row, kc), gbh + (size_t)c * 16);
                cp16(swz(sBlo[1], row, kc), gbl + (size_t)c * 16);
            }
            CP_COMMIT();
        }
    }

    // Per-thread ldmatrix row indices.
    int rl = lane & 15;                 // row within 16-row ldmatrix group
    int khalf = lane >> 4;              // +8 k for upper half
    float rs[8];
    #pragma unroll
    for (int q = 0; q < 8; ++q) rs[q] = 0.f;

    for (int k = 0; k < nt; ++k) {
        int p = k & 1;
        if (k + 1 < nt) asm volatile("cp.async.wait_group 1;" ::: "memory");
        else            asm volatile("cp.async.wait_group 0;" ::: "memory");
        __syncthreads();

        float acc[4][4][4];
        #pragma unroll
        for (int mi = 0; mi < 4; ++mi)
            #pragma unroll
            for (int ni = 0; ni < 4; ++ni)
                #pragma unroll
                for (int q = 0; q < 4; ++q) acc[mi][ni][q] = 0.f;

        #pragma unroll
        for (int ks = 0; ks < 8; ++ks) {
            int kc = ks * 2 + khalf;
            uint32_t ah[4][4], al[4][4], bh[2][4], bl[2][4];
            #pragma unroll
            for (int mi = 0; mi < 4; ++mi) {
                int row = wr * 64 + mi * 16 + rl;
                ldsm4(ah[mi], swz(sAhi, row, kc));
                ldsm4(al[mi], swz(sAlo, row, kc));
            }
            #pragma unroll
            for (int n2 = 0; n2 < 2; ++n2) {
                int row = wc * 32 + n2 * 16 + rl;
                ldsm4(bh[n2], swz(sBhi[p], row, kc));
                ldsm4(bl[n2], swz(sBlo[p], row, kc));
            }
            #pragma unroll
            for (int mi = 0; mi < 4; ++mi)
                #pragma unroll
                for (int ni = 0; ni < 4; ++ni) {
                    int n2 = ni >> 1, pr = ni & 1;
                    mma16816(acc[mi][ni], ah[mi], bh[n2][pr], bh[n2][pr + 2]);
                    mma16816(acc[mi][ni], ah[mi], bl[n2][pr], bl[n2][pr + 2]);
                    mma16816(acc[mi][ni], al[mi], bh[n2][pr], bh[n2][pr + 2]);
                }
        }
        __syncthreads();

        if (k + 2 < nt) {                   // prefetch B(k+2) into buffer p
            int t2 = chunk + (k + 2) * NCHUNK;
            const char* gbh = (const char*)d_Bhi + (size_t)t2 * 32768;
            const char* gbl = (const char*)d_Blo + (size_t)t2 * 32768;
            #pragma unroll
            for (int it = 0; it < 8; ++it) {
                int c = it * 256 + tid;
                int row = c >> 4, kc2 = c & 15;
                cp16(swz(sBhi[p], row, kc2), gbh + (size_t)c * 16);
                cp16(swz(sBlo[p], row, kc2), gbl + (size_t)c * 16);
            }
            CP_COMMIT();
        }

        // Fused exp + row accumulate.
        int cwarp = (chunk + k * NCHUNK) * 128 + wc * 32;
        if (cwarp + 32 <= Nn) {
            #pragma unroll
            for (int mi = 0; mi < 4; ++mi)
                #pragma unroll
                for (int ni = 0; ni < 4; ++ni) {
                    rs[mi * 2 + 0] += fexp5(acc[mi][ni][0]) + fexp5(acc[mi][ni][1]);
                    rs[mi * 2 + 1] += fexp5(acc[mi][ni][2]) + fexp5(acc[mi][ni][3]);
                }
        } else {
            #pragma unroll
            for (int mi = 0; mi < 4; ++mi)
                #pragma unroll
                for (int ni = 0; ni < 4; ++ni) {
                    int c0 = cwarp + ni * 8 + (lane & 3) * 2;
                    if (c0 < Nn) {
                        rs[mi * 2 + 0] += fexp5(acc[mi][ni][0]);
                        rs[mi * 2 + 1] += fexp5(acc[mi][ni][2]);
                    }
                    if (c0 + 1 < Nn) {
                        rs[mi * 2 + 0] += fexp5(acc[mi][ni][1]);
                        rs[mi * 2 + 1] += fexp5(acc[mi][ni][3]);
                    }
                }
        }
    }

    // Quad reduce (lanes sharing a row), then cross-warp-col reduce in smem.
    #pragma unroll
    for (int q = 0; q < 8; ++q) {
        rs[q] += __shfl_xor_sync(0xffffffffu, rs[q], 1);
        rs[q] += __shfl_xor_sync(0xffffffffu, rs[q], 2);
    }
    __syncthreads();
    float* sred = (float*)dyn;              // 128 rows x 4 warp-cols
    if ((lane & 3) == 0) {
        int g = lane >> 2;
        #pragma unroll
        for (int mi = 0; mi < 4; ++mi) {
            #pragma unroll
            for (int r8 = 0; r8 < 2; ++r8) {
                int row = wr * 64 + mi * 16 + r8 * 8 + g;
                sred[row * 4 + wc] = rs[mi * 2 + r8];
            }
        }
    }
    __syncthreads();
    if (tid < 128) {
        float s = sred[tid * 4] + sred[tid * 4 + 1] +
                  sred[tid * 4 + 2] + sred[tid * 4 + 3];
        d_Epart[(size_t)chunk * M + rowbase + tid] = s;
    }
}

// --------------------------- finalize + reduce -----------------------------

__global__ void finalize_kernel(const float* __restrict__ F,
                                const float* __restrict__ protos,
                                const int* __restrict__ labels,
                                int M, int B) {
    extern __shared__ float sP[];          // B*129 floats
    __shared__ float fR[8][128];
    int tid = threadIdx.x, lane = tid & 31, w = tid >> 5;

    for (int idx = tid; idx < B * 128; idx += 256) {
        int b = idx >> 7, k = idx & 127;
        sP[b * 129 + k] = protos[idx];
    }
    int i = blockIdx.x * 8 + w;
    {
        float4 v = *(const float4*)(F + (size_t)i * 128 + lane * 4);
        *(float4*)&fR[w][lane * 4] = v;
    }
    __syncthreads();

    float dg = 0.f, ds = 0.f;
    #pragma unroll
    for (int q = 0; q < 4; ++q) {
        float fv = fR[w][lane * 4 + q];
        dg = fmaf(fv, d_g[lane * 4 + q], dg);
        ds = fmaf(fv, fv, ds);
    }

    float psum = 0.f, pexp = 0.f, bipi = 0.f;
    int lab = labels[i];
    #pragma unroll
    for (int pb = 0; pb < 4; ++pb) {
        int b = lane + pb * 32;
        if (b < B) {
            float d = 0.f;
            #pragma unroll 8
            for (int k = 0; k < 128; ++k)
                d = fmaf(fR[w][k], sP[b * 129 + k], d);
            float P = d * 5.0f;
            psum += P;
            pexp += fexp(P);
            if (b == lab) bipi = P;
        }
    }
    #pragma unroll
    for (int off = 16; off; off >>= 1) {
        dg   += __shfl_xor_sync(0xffffffffu, dg, off);
        ds   += __shfl_xor_sync(0xffffffffu, ds, off);
        psum += __shfl_xor_sync(0xffffffffu, psum, off);
        pexp += __shfl_xor_sync(0xffffffffu, pexp, off);
        bipi += __shfl_xor_sync(0xffffffffu, bipi, off);
    }

    if (lane == 0) {
        float E = 0.f;
        #pragma unroll
        for (int c = 0; c < NCHUNK; ++c) E += d_Epart[(size_t)c * M + i];
        float loss;
        if (d_flag[i]) {
            float Sii = ds * 5.0f;
            float den = (E - fexp(Sii)) + psum;
            int cnt = d_Nn - 1;
            if (cnt > 0) {
                float sumS = dg * 5.0f - Sii;
                loss = -((sumS - logf(den) * (float)cnt) / (float)cnt);
            } else {
                loss = 0.f;
            }
        } else {
            loss = -(bipi - logf(E + pexp));
        }
        d_rowloss[i] = loss;
    }
}

__global__ void reduce_kernel(float* __restrict__ out, int M) {
    __shared__ float sm[1024];
    int tid = threadIdx.x;
    float s = 0.f;
    for (int i = tid; i < M; i += 1024) s += d_rowloss[i];
    sm[tid] = s;
    __syncthreads();
    for (int off = 512; off; off >>= 1) {
        if (tid < off) sm[tid] += sm[tid + off];
        __syncthreads();
    }
    if (tid == 0) out[0] = sm[0] / (float)M;
}

// ------------------------------- launcher ----------------------------------

extern "C" void kernel_launch(void* const* d_in, const int* in_sizes, int n_in,
                              void* d_out, int out_size) {
    const float* F      = (const float*)d_in[0];
    const int*   labels = (const int*)d_in[1];
    const float* protos = (const float*)d_in[2];
    const int*   plab   = (const int*)d_in[3];
    int M = in_sizes[1];                  // 8192
    int B = in_sizes[3];                  // 100

    scan_flags_kernel<<<1, 1024>>>(labels, plab, M, B);

    int convBlocks = (M * 16 + 128 * 16 + 255) / 256;
    convert_kernel<<<convBlocks, 256>>>(F, M);

    gpart_kernel<<<M / 32, 128>>>(F, M);
    gred_kernel<<<1, 128>>>(M / 32);

    size_t smemMain = 196608;             // 192 KB
    cudaFuncSetAttribute(mma_expsum_kernel,
                         cudaFuncAttributeMaxDynamicSharedMemorySize,
                         (int)smemMain);
    mma_expsum_kernel<<<dim3(M / 128, NCHUNK), 256, smemMain>>>(M);

    size_t smemP = (size_t)B * 129 * sizeof(float);
    cudaFuncSetAttribute(finalize_kernel,
                         cudaFuncAttributeMaxDynamicSharedMemorySize,
                         (int)smemP);
    finalize_kernel<<<M / 8, 256, smemP>>>(F, protos, labels, M, B);

    reduce_kernel<<<1, 1024>>>((float*)d_out, M);
}

// round 4
// speedup vs baseline: 2.5989x; 1.3878x over previous
#include <cuda_runtime.h>
#include <cuda_bf16.h>
#include <math.h>
#include <stdint.h>

// ---------------------------------------------------------------------------
// SupConLossWithPrototype via mma.sync bf16 (single-pass: bf16 rounding error
// ~7e-4 per logit, averages out in E; final rel err ~1e-5 << 1e-3).
//   E[i] = sum_{j novel} exp(f_i . f_j / T), fused poly-exp row-reduce.
// ---------------------------------------------------------------------------

#define MAXM 8192
#define NCHUNK 2

__device__ __align__(16) __nv_bfloat16 d_Ahi[(size_t)MAXM * 128];
__device__ __align__(16) __nv_bfloat16 d_Bhi[(size_t)(MAXM + 128) * 128];
__device__ int   d_pos[MAXM];
__device__ int   d_flag[MAXM];
__device__ int   d_Nn;
__device__ float d_gpart[64 * 128];
__device__ float d_g[128];
__device__ float d_Epart[(size_t)NCHUNK * MAXM];
__device__ float d_rowloss[MAXM];

// ------------------------------ helpers ------------------------------------

__device__ __forceinline__ uint32_t s2u(const void* p) {
    uint32_t a;
    asm("{ .reg .u64 t; cvta.to.shared.u64 t, %1; cvt.u32.u64 %0, t; }"
        : "=r"(a) : "l"(p));
    return a;
}

__device__ __forceinline__ void cp16(uint32_t s, const void* g) {
    asm volatile("cp.async.cg.shared.global [%0], [%1], 16;" :: "r"(s), "l"(g));
}
#define CP_COMMIT() asm volatile("cp.async.commit_group;" ::: "memory")

__device__ __forceinline__ void ldsm4(uint32_t (&r)[4], uint32_t addr) {
    asm volatile("ldmatrix.sync.aligned.m8n8.x4.shared.b16 {%0,%1,%2,%3}, [%4];"
                 : "=r"(r[0]), "=r"(r[1]), "=r"(r[2]), "=r"(r[3]) : "r"(addr));
}

__device__ __forceinline__ void mma16816(float (&d)[4], const uint32_t (&a)[4],
                                         uint32_t b0, uint32_t b1) {
    asm volatile(
        "mma.sync.aligned.m16n8k16.row.col.f32.bf16.bf16.f32 "
        "{%0,%1,%2,%3}, {%4,%5,%6,%7}, {%8,%9}, {%0,%1,%2,%3};"
        : "+f"(d[0]), "+f"(d[1]), "+f"(d[2]), "+f"(d[3])
        : "r"(a[0]), "r"(a[1]), "r"(a[2]), "r"(a[3]), "r"(b0), "r"(b1));
}

// XOR-swizzled smem tile: 128 rows x 256B row. chunk' = chunk ^ (row & 7).
__device__ __forceinline__ uint32_t swz(uint32_t base, int row, int kchunk) {
    return base + row * 256 + (((uint32_t)(kchunk ^ (row & 7))) << 4);
}

// exp(5x) on the FMA pipe, rel err ~1.5e-7, |5x| < ~80.
__device__ __forceinline__ float fexp5(float x) {
    const float L = 7.2134752044448170f;      // 5 * log2(e)
    float z = fmaf(x, L, 12582912.0f);
    int   ki = __float_as_int(z) - 0x4B400000;
    float r = fmaf(x, L, 12582912.0f - z);
    float p =      1.5403530393381610e-4f;
    p = fmaf(p, r, 1.3333558146428443e-3f);
    p = fmaf(p, r, 9.6181291076284772e-3f);
    p = fmaf(p, r, 5.5504108664821580e-2f);
    p = fmaf(p, r, 2.4022650695910072e-1f);
    p = fmaf(p, r, 6.9314718055994531e-1f);
    p = fmaf(p, r, 1.0f);
    return __int_as_float(__float_as_int(p) + (ki << 23));
}

__device__ __forceinline__ float fexp(float x) {
    float t = x * 1.4426950408889634f;
    float z = t + 12582912.0f;
    int   ki = __float_as_int(z) - 0x4B400000;
    float r = t - (z - 12582912.0f);
    float p =      1.5403530393381610e-4f;
    p = fmaf(p, r, 1.3333558146428443e-3f);
    p = fmaf(p, r, 9.6181291076284772e-3f);
    p = fmaf(p, r, 5.5504108664821580e-2f);
    p = fmaf(p, r, 2.4022650695910072e-1f);
    p = fmaf(p, r, 6.9314718055994531e-1f);
    p = fmaf(p, r, 1.0f);
    return __int_as_float(__float_as_int(p) + (ki << 23));
}

// --------------------------- setup kernels --------------------------------

__global__ void scan_flags_kernel(const int* __restrict__ labels,
                                  const int* __restrict__ plab, int M, int B) {
    __shared__ int sPL[128];
    __shared__ int sWarp[32];
    __shared__ int sBase, sTot;
    int tid = threadIdx.x, lane = tid & 31, wid = tid >> 5;
    if (tid < B) sPL[tid] = plab[tid];
    if (tid == 0) sBase = 0;
    __syncthreads();
    for (int c0 = 0; c0 < M; c0 += 1024) {
        int i = c0 + tid;
        int f = 0;
        if (i < M) {
            int lab = labels[i];
            int hit = 0;
            for (int b = 0; b < B; ++b) hit |= (lab == sPL[b]);
            f = hit ^ 1;
            d_flag[i] = f;
        }
        unsigned bal = __ballot_sync(0xffffffffu, f != 0);
        int lanePre = __popc(bal & ((1u << lane) - 1u));
        if (lane == 0) sWarp[wid] = __popc(bal);
        __syncthreads();
        if (wid == 0) {
            int v = sWarp[lane];
            int pre = v;
            #pragma unroll
            for (int off = 1; off < 32; off <<= 1) {
                int n = __shfl_up_sync(0xffffffffu, pre, off);
                if (lane >= off) pre += n;
            }
            sWarp[lane] = pre - v;
            if (lane == 31) sTot = pre;
        }
        __syncthreads();
        if (i < M && f) d_pos[i] = sBase + sWarp[wid] + lanePre;
        __syncthreads();
        if (tid == 0) sBase += sTot;
        __syncthreads();
    }
    if (tid == 0) d_Nn = sBase;
}

// Round features to bf16; row-major A (all rows) and B (compacted novel
// rows). Tail zeros the pad rows of the last B tile.
__global__ void convert_kernel(const float* __restrict__ F, int M) {
    int idx = blockIdx.x * 256 + threadIdx.x;
    int total = M * 16;
    if (idx < total) {
        int r = idx >> 4, kc = idx & 15;
        float4 v0 = *(const float4*)(F + (size_t)r * 128 + kc * 8);
        float4 v1 = *(const float4*)(F + (size_t)r * 128 + kc * 8 + 4);
        float av[8] = {v0.x, v0.y, v0.z, v0.w, v1.x, v1.y, v1.z, v1.w};
        union { __nv_bfloat16 h[8]; uint4 u; } ph;
        #pragma unroll
        for (int q = 0; q < 8; ++q) ph.h[q] = __float2bfloat16(av[q]);
        ((uint4*)d_Ahi)[(size_t)r * 16 + kc] = ph.u;
        if (d_flag[r])
            ((uint4*)d_Bhi)[(size_t)d_pos[r] * 16 + kc] = ph.u;
    } else {
        int idx2 = idx - total;
        if (idx2 < 128 * 16) {
            int Nn = d_Nn;
            int pad = ((Nn + 127) & ~127) - Nn;
            int trow = idx2 >> 4, kc = idx2 & 15;
            if (trow < pad)
                ((uint4*)d_Bhi)[(size_t)(Nn + trow) * 16 + kc] =
                    make_uint4(0, 0, 0, 0);
        }
    }
}

__global__ void gpart_kernel(const float* __restrict__ F, int M) {
    int k = threadIdx.x;
    int r0 = blockIdx.x * 128;
    int r1 = min(r0 + 128, M);
    float s = 0.f;
    for (int r = r0; r < r1; ++r)
        if (d_flag[r]) s += F[(size_t)r * 128 + k];
    d_gpart[blockIdx.x * 128 + k] = s;
}

__global__ void gred_kernel(int nb) {          // nb = 64, block = 1024
    __shared__ float sm[1024];
    int t = threadIdx.x;
    int k = t & 127, p = t >> 7;               // 8 partial groups
    float s = 0.f;
    for (int b = p; b < nb; b += 8) s += d_gpart[b * 128 + k];
    sm[t] = s;
    __syncthreads();
    if (p == 0) {
        float tot = sm[k];
        #pragma unroll
        for (int q = 1; q < 8; ++q) tot += sm[q * 128 + k];
        d_g[k] = tot;
    }
}

// ---------------------- main mma.sync exp-sum kernel -----------------------
// CTA: 128 rows x stream of 128-col novel tiles (stride NCHUNK).
// smem: A resident (32KB) + B double buffer (64KB) = 96KB.
// 8 warps in 2x4 grid, warp tile 64x32, single-pass bf16 mma.

__global__ __launch_bounds__(256, 1) void mma_expsum_kernel(int M) {
    extern __shared__ char dyn[];
    const uint32_t sbase = s2u(dyn);
    const uint32_t sA = sbase;
    const uint32_t sB[2] = {sbase + 32768, sbase + 65536};

    int tid = threadIdx.x;
    int lane = tid & 31, w = tid >> 5;
    int wr = w >> 2, wc = w & 3;               // warp grid 2 x 4
    int rowbase = blockIdx.x * 128;
    int chunk = blockIdx.y;
    int Nn = d_Nn;
    int ntiles = (Nn + 127) >> 7;
    int nt = (ntiles > chunk) ? ((ntiles - chunk + NCHUNK - 1) / NCHUNK) : 0;

    // Prologue: A (group 0, with B0) + B1 (group 1).
    {
        const char* ga = (const char*)d_Ahi + (size_t)blockIdx.x * 32768;
        #pragma unroll
        for (int it = 0; it < 8; ++it) {
            int c = it * 256 + tid;
            cp16(swz(sA, c >> 4, c & 15), ga + (size_t)c * 16);
        }
        if (nt > 0) {
            const char* gb = (const char*)d_Bhi + (size_t)chunk * 32768;
            #pragma unroll
            for (int it = 0; it < 8; ++it) {
                int c = it * 256 + tid;
                cp16(swz(sB[0], c >> 4, c & 15), gb + (size_t)c * 16);
            }
        }
        CP_COMMIT();
        if (nt > 1) {
            const char* gb = (const char*)d_Bhi + (size_t)(chunk + NCHUNK) * 32768;
            #pragma unroll
            for (int it = 0; it < 8; ++it) {
                int c = it * 256 + tid;
                cp16(swz(sB[1], c >> 4, c & 15), gb + (size_t)c * 16);
            }
            CP_COMMIT();
        }
    }

    int rl = lane & 15;                 // ldmatrix row within 16-row group
    int khalf = lane >> 4;              // +1 k-chunk for upper half
    float rs[8];
    #pragma unroll
    for (int q = 0; q < 8; ++q) rs[q] = 0.f;

    for (int k = 0; k < nt; ++k) {
        int p = k & 1;
        if (k + 1 < nt) asm volatile("cp.async.wait_group 1;" ::: "memory");
        else            asm volatile("cp.async.wait_group 0;" ::: "memory");
        __syncthreads();

        float acc[4][4][4];
        #pragma unroll
        for (int mi = 0; mi < 4; ++mi)
            #pragma unroll
            for (int ni = 0; ni < 4; ++ni)
                #pragma unroll
                for (int q = 0; q < 4; ++q) acc[mi][ni][q] = 0.f;

        #pragma unroll
        for (int ks = 0; ks < 8; ++ks) {
            int kc = ks * 2 + khalf;
            uint32_t a[4][4], b[2][4];
            #pragma unroll
            for (int mi = 0; mi < 4; ++mi)
                ldsm4(a[mi], swz(sA, wr * 64 + mi * 16 + rl, kc));
            #pragma unroll
            for (int n2 = 0; n2 < 2; ++n2)
                ldsm4(b[n2], swz(sB[p], wc * 32 + n2 * 16 + rl, kc));
            #pragma unroll
            for (int mi = 0; mi < 4; ++mi)
                #pragma unroll
                for (int ni = 0; ni < 4; ++ni) {
                    int n2 = ni >> 1, pr = ni & 1;
                    mma16816(acc[mi][ni], a[mi], b[n2][pr], b[n2][pr + 2]);
                }
        }
        __syncthreads();

        if (k + 2 < nt) {                   // prefetch B(k+2) into buffer p
            const char* gb = (const char*)d_Bhi +
                             (size_t)(chunk + (k + 2) * NCHUNK) * 32768;
            #pragma unroll
            for (int it = 0; it < 8; ++it) {
                int c = it * 256 + tid;
                cp16(swz(sB[p], c >> 4, c & 15), gb + (size_t)c * 16);
            }
            CP_COMMIT();
        }

        // Fused exp + row accumulate.
        int cwarp = (chunk + k * NCHUNK) * 128 + wc * 32;
        if (cwarp + 32 <= Nn) {
            #pragma unroll
            for (int mi = 0; mi < 4; ++mi)
                #pragma unroll
                for (int ni = 0; ni < 4; ++ni) {
                    rs[mi * 2 + 0] += fexp5(acc[mi][ni][0]) + fexp5(acc[mi][ni][1]);
                    rs[mi * 2 + 1] += fexp5(acc[mi][ni][2]) + fexp5(acc[mi][ni][3]);
                }
        } else {
            #pragma unroll
            for (int mi = 0; mi < 4; ++mi)
                #pragma unroll
                for (int ni = 0; ni < 4; ++ni) {
                    int c0 = cwarp + ni * 8 + (lane & 3) * 2;
                    if (c0 < Nn) {
                        rs[mi * 2 + 0] += fexp5(acc[mi][ni][0]);
                        rs[mi * 2 + 1] += fexp5(acc[mi][ni][2]);
                    }
                    if (c0 + 1 < Nn) {
                        rs[mi * 2 + 0] += fexp5(acc[mi][ni][1]);
                        rs[mi * 2 + 1] += fexp5(acc[mi][ni][3]);
                    }
                }
        }
    }

    // Quad reduce (lanes sharing a row), then cross-warp-col reduce in smem.
    #pragma unroll
    for (int q = 0; q < 8; ++q) {
        rs[q] += __shfl_xor_sync(0xffffffffu, rs[q], 1);
        rs[q] += __shfl_xor_sync(0xffffffffu, rs[q], 2);
    }
    __syncthreads();
    float* sred = (float*)dyn;              // 128 rows x 4 warp-cols
    if ((lane & 3) == 0) {
        int g = lane >> 2;
        #pragma unroll
        for (int mi = 0; mi < 4; ++mi)
            #pragma unroll
            for (int r8 = 0; r8 < 2; ++r8) {
                int row = wr * 64 + mi * 16 + r8 * 8 + g;
                sred[row * 4 + wc] = rs[mi * 2 + r8];
            }
    }
    __syncthreads();
    if (tid < 128) {
        float s = sred[tid * 4] + sred[tid * 4 + 1] +
                  sred[tid * 4 + 2] + sred[tid * 4 + 3];
        d_Epart[(size_t)chunk * M + rowbase + tid] = s;
    }
}

// --------------------------- finalize + reduce -----------------------------

__global__ void finalize_kernel(const float* __restrict__ F,
                                const float* __restrict__ protos,
                                const int* __restrict__ labels,
                                int M, int B) {
    extern __shared__ float sP[];          // B*129 floats
    __shared__ float fR[8][128];
    int tid = threadIdx.x, lane = tid & 31, w = tid >> 5;

    for (int idx = tid; idx < B * 128; idx += 256) {
        int b = idx >> 7, k = idx & 127;
        sP[b * 129 + k] = protos[idx];
    }
    int i = blockIdx.x * 8 + w;
    {
        float4 v = *(const float4*)(F + (size_t)i * 128 + lane * 4);
        *(float4*)&fR[w][lane * 4] = v;
    }
    __syncthreads();

    float dg = 0.f, ds = 0.f;
    #pragma unroll
    for (int q = 0; q < 4; ++q) {
        float fv = fR[w][lane * 4 + q];
        dg = fmaf(fv, d_g[lane * 4 + q], dg);
        ds = fmaf(fv, fv, ds);
    }

    float psum = 0.f, pexp = 0.f, bipi = 0.f;
    int lab = labels[i];
    #pragma unroll
    for (int pb = 0; pb < 4; ++pb) {
        int b = lane + pb * 32;
        if (b < B) {
            float d = 0.f;
            #pragma unroll 8
            for (int k = 0; k < 128; ++k)
                d = fmaf(fR[w][k], sP[b * 129 + k], d);
            float P = d * 5.0f;
            psum += P;
            pexp += fexp(P);
            if (b == lab) bipi = P;
        }
    }
    #pragma unroll
    for (int off = 16; off; off >>= 1) {
        dg   += __shfl_xor_sync(0xffffffffu, dg, off);
        ds   += __shfl_xor_sync(0xffffffffu, ds, off);
        psum += __shfl_xor_sync(0xffffffffu, psum, off);
        pexp += __shfl_xor_sync(0xffffffffu, pexp, off);
        bipi += __shfl_xor_sync(0xffffffffu, bipi, off);
    }

    if (lane == 0) {
        float E = 0.f;
        #pragma unroll
        for (int c = 0; c < NCHUNK; ++c) E += d_Epart[(size_t)c * M + i];
        float loss;
        if (d_flag[i]) {
            float Sii = ds * 5.0f;
            float den = (E - fexp(Sii)) + psum;
            int cnt = d_Nn - 1;
            if (cnt > 0) {
                float sumS = dg * 5.0f - Sii;
                loss = -((sumS - logf(den) * (float)cnt) / (float)cnt);
            } else {
                loss = 0.f;
            }
        } else {
            loss = -(bipi - logf(E + pexp));
        }
        d_rowloss[i] = loss;
    }
}

__global__ void reduce_kernel(float* __restrict__ out, int M) {
    __shared__ float sm[1024];
    int tid = threadIdx.x;
    float s = 0.f;
    for (int i = tid; i < M; i += 1024) s += d_rowloss[i];
    sm[tid] = s;
    __syncthreads();
    for (int off = 512; off; off >>= 1) {
        if (tid < off) sm[tid] += sm[tid + off];
        __syncthreads();
    }
    if (tid == 0) out[0] = sm[0] / (float)M;
}

// ------------------------------- launcher ----------------------------------

extern "C" void kernel_launch(void* const* d_in, const int* in_sizes, int n_in,
                              void* d_out, int out_size) {
    const float* F      = (const float*)d_in[0];
    const int*   labels = (const int*)d_in[1];
    const float* protos = (const float*)d_in[2];
    const int*   plab   = (const int*)d_in[3];
    int M = in_sizes[1];                  // 8192
    int B = in_sizes[3];                  // 100

    scan_flags_kernel<<<1, 1024>>>(labels, plab, M, B);

    int convBlocks = (M * 16 + 128 * 16 + 255) / 256;
    convert_kernel<<<convBlocks, 256>>>(F, M);

    gpart_kernel<<<M / 128, 128>>>(F, M);
    gred_kernel<<<1, 1024>>>(M / 128);

    size_t smemMain = 98304;              // 96 KB
    cudaFuncSetAttribute(mma_expsum_kernel,
                         cudaFuncAttributeMaxDynamicSharedMemorySize,
                         (int)smemMain);
    mma_expsum_kernel<<<dim3(M / 128, NCHUNK), 256, smemMain>>>(M);

    size_t smemP = (size_t)B * 129 * sizeof(float);
    cudaFuncSetAttribute(finalize_kernel,
                         cudaFuncAttributeMaxDynamicSharedMemorySize,
                         (int)smemP);
    finalize_kernel<<<M / 8, 256, smemP>>>(F, protos, labels, M, B);

    reduce_kernel<<<1, 1024>>>((float*)d_out, M);
}

// round 5
// speedup vs baseline: 2.6893x; 1.0348x over previous
#include <cuda_runtime.h>
#include <cuda_bf16.h>
#include <math.h>
#include <stdint.h>

// ---------------------------------------------------------------------------
// SupConLossWithPrototype via mma.sync bf16, MUFU-pipe exp epilogue.
//   E[i] = sum_{j novel} exp(f_i . f_j / T), fused ex2 row-reduce.
// ---------------------------------------------------------------------------

#define MAXM 8192
#define NCHUNK 4

__device__ __align__(16) __nv_bfloat16 d_Ahi[(size_t)MAXM * 128];
__device__ __align__(16) __nv_bfloat16 d_Bhi[(size_t)(MAXM + 128) * 128];
__device__ int   d_pos[MAXM];
__device__ int   d_flag[MAXM];
__device__ int   d_Nn;
__device__ float d_gpart[64 * 128];
__device__ float d_g[128];
__device__ float d_Epart[(size_t)NCHUNK * MAXM];
__device__ float d_rowloss[MAXM];

// ------------------------------ helpers ------------------------------------

__device__ __forceinline__ uint32_t s2u(const void* p) {
    uint32_t a;
    asm("{ .reg .u64 t; cvta.to.shared.u64 t, %1; cvt.u32.u64 %0, t; }"
        : "=r"(a) : "l"(p));
    return a;
}

__device__ __forceinline__ void cp16(uint32_t s, const void* g) {
    asm volatile("cp.async.cg.shared.global [%0], [%1], 16;" :: "r"(s), "l"(g));
}
#define CP_COMMIT() asm volatile("cp.async.commit_group;" ::: "memory")

__device__ __forceinline__ void ldsm4(uint32_t (&r)[4], uint32_t addr) {
    asm volatile("ldmatrix.sync.aligned.m8n8.x4.shared.b16 {%0,%1,%2,%3}, [%4];"
                 : "=r"(r[0]), "=r"(r[1]), "=r"(r[2]), "=r"(r[3]) : "r"(addr));
}

__device__ __forceinline__ void mma16816(float (&d)[4], const uint32_t (&a)[4],
                                         uint32_t b0, uint32_t b1) {
    asm volatile(
        "mma.sync.aligned.m16n8k16.row.col.f32.bf16.bf16.f32 "
        "{%0,%1,%2,%3}, {%4,%5,%6,%7}, {%8,%9}, {%0,%1,%2,%3};"
        : "+f"(d[0]), "+f"(d[1]), "+f"(d[2]), "+f"(d[3])
        : "r"(a[0]), "r"(a[1]), "r"(a[2]), "r"(a[3]), "r"(b0), "r"(b1));
}

// XOR-swizzled smem tile: 128 rows x 256B row. chunk' = chunk ^ (row & 7).
__device__ __forceinline__ uint32_t swz(uint32_t base, int row, int kchunk) {
    return base + row * 256 + (((uint32_t)(kchunk ^ (row & 7))) << 4);
}

// exp(5x) via MUFU.EX2 (SFU pipe, off the FMA/tensor critical path).
#define LOG2E5 7.2134752044448170f
__device__ __forceinline__ float ex2f(float t) {
    float r;
    asm("ex2.approx.f32 %0, %1;" : "=f"(r) : "f"(t));
    return r;
}

// exp on the FMA pipe (setup/finalize use only), rel err ~1.5e-7.
__device__ __forceinline__ float fexp(float x) {
    float t = x * 1.4426950408889634f;
    float z = t + 12582912.0f;
    int   ki = __float_as_int(z) - 0x4B400000;
    float r = t - (z - 12582912.0f);
    float p =      1.5403530393381610e-4f;
    p = fmaf(p, r, 1.3333558146428443e-3f);
    p = fmaf(p, r, 9.6181291076284772e-3f);
    p = fmaf(p, r, 5.5504108664821580e-2f);
    p = fmaf(p, r, 2.4022650695910072e-1f);
    p = fmaf(p, r, 6.9314718055994531e-1f);
    p = fmaf(p, r, 1.0f);
    return __int_as_float(__float_as_int(p) + (ki << 23));
}

// --------------------------- setup kernels --------------------------------

__global__ void scan_flags_kernel(const int* __restrict__ labels,
                                  const int* __restrict__ plab, int M, int B) {
    __shared__ int sPL[128];
    __shared__ int sWarp[32];
    __shared__ int sBase, sTot;
    int tid = threadIdx.x, lane = tid & 31, wid = tid >> 5;
    if (tid < B) sPL[tid] = plab[tid];
    if (tid == 0) sBase = 0;
    __syncthreads();
    for (int c0 = 0; c0 < M; c0 += 1024) {
        int i = c0 + tid;
        int f = 0;
        if (i < M) {
            int lab = labels[i];
            int hit = 0;
            for (int b = 0; b < B; ++b) hit |= (lab == sPL[b]);
            f = hit ^ 1;
            d_flag[i] = f;
        }
        unsigned bal = __ballot_sync(0xffffffffu, f != 0);
        int lanePre = __popc(bal & ((1u << lane) - 1u));
        if (lane == 0) sWarp[wid] = __popc(bal);
        __syncthreads();
        if (wid == 0) {
            int v = sWarp[lane];
            int pre = v;
            #pragma unroll
            for (int off = 1; off < 32; off <<= 1) {
                int n = __shfl_up_sync(0xffffffffu, pre, off);
                if (lane >= off) pre += n;
            }
            sWarp[lane] = pre - v;
            if (lane == 31) sTot = pre;
        }
        __syncthreads();
        if (i < M && f) d_pos[i] = sBase + sWarp[wid] + lanePre;
        __syncthreads();
        if (tid == 0) sBase += sTot;
        __syncthreads();
    }
    if (tid == 0) d_Nn = sBase;
}

// Round features to bf16; row-major A (all rows) and B (compacted novel
// rows). Tail zeros the pad rows of the last B tile.
__global__ void convert_kernel(const float* __restrict__ F, int M) {
    int idx = blockIdx.x * 256 + threadIdx.x;
    int total = M * 16;
    if (idx < total) {
        int r = idx >> 4, kc = idx & 15;
        float4 v0 = *(const float4*)(F + (size_t)r * 128 + kc * 8);
        float4 v1 = *(const float4*)(F + (size_t)r * 128 + kc * 8 + 4);
        float av[8] = {v0.x, v0.y, v0.z, v0.w, v1.x, v1.y, v1.z, v1.w};
        union { __nv_bfloat16 h[8]; uint4 u; } ph;
        #pragma unroll
        for (int q = 0; q < 8; ++q) ph.h[q] = __float2bfloat16(av[q]);
        ((uint4*)d_Ahi)[(size_t)r * 16 + kc] = ph.u;
        if (d_flag[r])
            ((uint4*)d_Bhi)[(size_t)d_pos[r] * 16 + kc] = ph.u;
    } else {
        int idx2 = idx - total;
        if (idx2 < 128 * 16) {
            int Nn = d_Nn;
            int pad = ((Nn + 127) & ~127) - Nn;
            int trow = idx2 >> 4, kc = idx2 & 15;
            if (trow < pad)
                ((uint4*)d_Bhi)[(size_t)(Nn + trow) * 16 + kc] =
                    make_uint4(0, 0, 0, 0);
        }
    }
}

__global__ void gpart_kernel(const float* __restrict__ F, int M) {
    int k = threadIdx.x;
    int r0 = blockIdx.x * 128;
    int r1 = min(r0 + 128, M);
    float s = 0.f;
    for (int r = r0; r < r1; ++r)
        if (d_flag[r]) s += F[(size_t)r * 128 + k];
    d_gpart[blockIdx.x * 128 + k] = s;
}

__global__ void gred_kernel(int nb) {          // nb = 64, block = 1024
    __shared__ float sm[1024];
    int t = threadIdx.x;
    int k = t & 127, p = t >> 7;
    float s = 0.f;
    for (int b = p; b < nb; b += 8) s += d_gpart[b * 128 + k];
    sm[t] = s;
    __syncthreads();
    if (p == 0) {
        float tot = sm[k];
        #pragma unroll
        for (int q = 1; q < 8; ++q) tot += sm[q * 128 + k];
        d_g[k] = tot;
    }
}

// ---------------------- main mma.sync exp-sum kernel -----------------------
// CTA: 128 rows x stream of 128-col novel tiles (stride NCHUNK).
// smem: A resident (32KB) + B double buffer (64KB) = 96KB.
// 8 warps in 2x4 grid, warp tile 64x32, single-pass bf16 mma, MUFU exp.

__global__ __launch_bounds__(256, 1) void mma_expsum_kernel(int M) {
    extern __shared__ char dyn[];
    const uint32_t sbase = s2u(dyn);
    const uint32_t sA = sbase;
    const uint32_t sB[2] = {sbase + 32768, sbase + 65536};

    int tid = threadIdx.x;
    int lane = tid & 31, w = tid >> 5;
    int wr = w >> 2, wc = w & 3;               // warp grid 2 x 4
    int rowbase = blockIdx.x * 128;
    int chunk = blockIdx.y;
    int Nn = d_Nn;
    int ntiles = (Nn + 127) >> 7;
    int nt = (ntiles > chunk) ? ((ntiles - chunk + NCHUNK - 1) / NCHUNK) : 0;

    // Prologue: A (group 0, with B0) + B1 (group 1).
    {
        const char* ga = (const char*)d_Ahi + (size_t)blockIdx.x * 32768;
        #pragma unroll
        for (int it = 0; it < 8; ++it) {
            int c = it * 256 + tid;
            cp16(swz(sA, c >> 4, c & 15), ga + (size_t)c * 16);
        }
        if (nt > 0) {
            const char* gb = (const char*)d_Bhi + (size_t)chunk * 32768;
            #pragma unroll
            for (int it = 0; it < 8; ++it) {
                int c = it * 256 + tid;
                cp16(swz(sB[0], c >> 4, c & 15), gb + (size_t)c * 16);
            }
        }
        CP_COMMIT();
        if (nt > 1) {
            const char* gb = (const char*)d_Bhi + (size_t)(chunk + NCHUNK) * 32768;
            #pragma unroll
            for (int it = 0; it < 8; ++it) {
                int c = it * 256 + tid;
                cp16(swz(sB[1], c >> 4, c & 15), gb + (size_t)c * 16);
            }
            CP_COMMIT();
        }
    }

    int rl = lane & 15;                 // ldmatrix row within 16-row group
    int khalf = lane >> 4;              // +1 k-chunk for upper half
    float rs[8];
    #pragma unroll
    for (int q = 0; q < 8; ++q) rs[q] = 0.f;

    for (int k = 0; k < nt; ++k) {
        int p = k & 1;
        if (k + 1 < nt) asm volatile("cp.async.wait_group 1;" ::: "memory");
        else            asm volatile("cp.async.wait_group 0;" ::: "memory");
        __syncthreads();

        float acc[4][4][4];
        #pragma unroll
        for (int mi = 0; mi < 4; ++mi)
            #pragma unroll
            for (int ni = 0; ni < 4; ++ni)
                #pragma unroll
                for (int q = 0; q < 4; ++q) acc[mi][ni][q] = 0.f;

        #pragma unroll
        for (int ks = 0; ks < 8; ++ks) {
            int kc = ks * 2 + khalf;
            uint32_t a[4][4], b[2][4];
            #pragma unroll
            for (int mi = 0; mi < 4; ++mi)
                ldsm4(a[mi], swz(sA, wr * 64 + mi * 16 + rl, kc));
            #pragma unroll
            for (int n2 = 0; n2 < 2; ++n2)
                ldsm4(b[n2], swz(sB[p], wc * 32 + n2 * 16 + rl, kc));
            #pragma unroll
            for (int mi = 0; mi < 4; ++mi)
                #pragma unroll
                for (int ni = 0; ni < 4; ++ni) {
                    int n2 = ni >> 1, pr = ni & 1;
                    mma16816(acc[mi][ni], a[mi], b[n2][pr], b[n2][pr + 2]);
                }
        }
        __syncthreads();

        if (k + 2 < nt) {                   // prefetch B(k+2) into buffer p
            const char* gb = (const char*)d_Bhi +
                             (size_t)(chunk + (k + 2) * NCHUNK) * 32768;
            #pragma unroll
            for (int it = 0; it < 8; ++it) {
                int c = it * 256 + tid;
                cp16(swz(sB[p], c >> 4, c & 15), gb + (size_t)c * 16);
            }
            CP_COMMIT();
        }

        // Fused exp + row accumulate (MUFU pipe).
        int cwarp = (chunk + k * NCHUNK) * 128 + wc * 32;
        if (cwarp + 32 <= Nn) {
            #pragma unroll
            for (int mi = 0; mi < 4; ++mi)
                #pragma unroll
                for (int ni = 0; ni < 4; ++ni) {
                    rs[mi * 2 + 0] += ex2f(acc[mi][ni][0] * LOG2E5) +
                                      ex2f(acc[mi][ni][1] * LOG2E5);
                    rs[mi * 2 + 1] += ex2f(acc[mi][ni][2] * LOG2E5) +
                                      ex2f(acc[mi][ni][3] * LOG2E5);
                }
        } else {
            #pragma unroll
            for (int mi = 0; mi < 4; ++mi)
                #pragma unroll
                for (int ni = 0; ni < 4; ++ni) {
                    int c0 = cwarp + ni * 8 + (lane & 3) * 2;
                    float t0 = (c0     < Nn) ? acc[mi][ni][0] * LOG2E5 : -1e30f;
                    float t1 = (c0 + 1 < Nn) ? acc[mi][ni][1] * LOG2E5 : -1e30f;
                    float t2 = (c0     < Nn) ? acc[mi][ni][2] * LOG2E5 : -1e30f;
                    float t3 = (c0 + 1 < Nn) ? acc[mi][ni][3] * LOG2E5 : -1e30f;
                    rs[mi * 2 + 0] += ex2f(t0) + ex2f(t1);
                    rs[mi * 2 + 1] += ex2f(t2) + ex2f(t3);
                }
        }
    }

    // Quad reduce (lanes sharing a row), then cross-warp-col reduce in smem.
    #pragma unroll
    for (int q = 0; q < 8; ++q) {
        rs[q] += __shfl_xor_sync(0xffffffffu, rs[q], 1);
        rs[q] += __shfl_xor_sync(0xffffffffu, rs[q], 2);
    }
    __syncthreads();
    float* sred = (float*)dyn;              // 128 rows x 4 warp-cols
    if ((lane & 3) == 0) {
        int g = lane >> 2;
        #pragma unroll
        for (int mi = 0; mi < 4; ++mi)
            #pragma unroll
            for (int r8 = 0; r8 < 2; ++r8) {
                int row = wr * 64 + mi * 16 + r8 * 8 + g;
                sred[row * 4 + wc] = rs[mi * 2 + r8];
            }
    }
    __syncthreads();
    if (tid < 128) {
        float s = sred[tid * 4] + sred[tid * 4 + 1] +
                  sred[tid * 4 + 2] + sred[tid * 4 + 3];
        d_Epart[(size_t)chunk * M + rowbase + tid] = s;
    }
}

// --------------------------- finalize + reduce -----------------------------

__global__ void finalize_kernel(const float* __restrict__ F,
                                const float* __restrict__ protos,
                                const int* __restrict__ labels,
                                int M, int B) {
    extern __shared__ float sP[];          // B*129 floats
    __shared__ float fR[8][128];
    int tid = threadIdx.x, lane = tid & 31, w = tid >> 5;

    for (int idx = tid; idx < B * 128; idx += 256) {
        int b = idx >> 7, k = idx & 127;
        sP[b * 129 + k] = protos[idx];
    }
    int i = blockIdx.x * 8 + w;
    {
        float4 v = *(const float4*)(F + (size_t)i * 128 + lane * 4);
        *(float4*)&fR[w][lane * 4] = v;
    }
    __syncthreads();

    float dg = 0.f, ds = 0.f;
    #pragma unroll
    for (int q = 0; q < 4; ++q) {
        float fv = fR[w][lane * 4 + q];
        dg = fmaf(fv, d_g[lane * 4 + q], dg);
        ds = fmaf(fv, fv, ds);
    }

    float psum = 0.f, pexp = 0.f, bipi = 0.f;
    int lab = labels[i];
    #pragma unroll
    for (int pb = 0; pb < 4; ++pb) {
        int b = lane + pb * 32;
        if (b < B) {
            float d = 0.f;
            #pragma unroll 8
            for (int k = 0; k < 128; ++k)
                d = fmaf(fR[w][k], sP[b * 129 + k], d);
            float P = d * 5.0f;
            psum += P;
            pexp += fexp(P);
            if (b == lab) bipi = P;
        }
    }
    #pragma unroll
    for (int off = 16; off; off >>= 1) {
        dg   += __shfl_xor_sync(0xffffffffu, dg, off);
        ds   += __shfl_xor_sync(0xffffffffu, ds, off);
        psum += __shfl_xor_sync(0xffffffffu, psum, off);
        pexp += __shfl_xor_sync(0xffffffffu, pexp, off);
        bipi += __shfl_xor_sync(0xffffffffu, bipi, off);
    }

    if (lane == 0) {
        float E = 0.f;
        #pragma unroll
        for (int c = 0; c < NCHUNK; ++c) E += d_Epart[(size_t)c * M + i];
        float loss;
        if (d_flag[i]) {
            float Sii = ds * 5.0f;
            float den = (E - fexp(Sii)) + psum;
            int cnt = d_Nn - 1;
            if (cnt > 0) {
                float sumS = dg * 5.0f - Sii;
                loss = -((sumS - logf(den) * (float)cnt) / (float)cnt);
            } else {
                loss = 0.f;
            }
        } else {
            loss = -(bipi - logf(E + pexp));
        }
        d_rowloss[i] = loss;
    }
}

__global__ void reduce_kernel(float* __restrict__ out, int M) {
    __shared__ float sm[1024];
    int tid = threadIdx.x;
    float s = 0.f;
    for (int i = tid; i < M; i += 1024) s += d_rowloss[i];
    sm[tid] = s;
    __syncthreads();
    for (int off = 512; off; off >>= 1) {
        if (tid < off) sm[tid] += sm[tid + off];
        __syncthreads();
    }
    if (tid == 0) out[0] = sm[0] / (float)M;
}

// ------------------------------- launcher ----------------------------------

extern "C" void kernel_launch(void* const* d_in, const int* in_sizes, int n_in,
                              void* d_out, int out_size) {
    const float* F      = (const float*)d_in[0];
    const int*   labels = (const int*)d_in[1];
    const float* protos = (const float*)d_in[2];
    const int*   plab   = (const int*)d_in[3];
    int M = in_sizes[1];                  // 8192
    int B = in_sizes[3];                  // 100

    scan_flags_kernel<<<1, 1024>>>(labels, plab, M, B);

    int convBlocks = (M * 16 + 128 * 16 + 255) / 256;
    convert_kernel<<<convBlocks, 256>>>(F, M);

    gpart_kernel<<<M / 128, 128>>>(F, M);
    gred_kernel<<<1, 1024>>>(M / 128);

    size_t smemMain = 98304;              // 96 KB
    cudaFuncSetAttribute(mma_expsum_kernel,
                         cudaFuncAttributeMaxDynamicSharedMemorySize,
                         (int)smemMain);
    mma_expsum_kernel<<<dim3(M / 128, NCHUNK), 256, smemMain>>>(M);

    size_t smemP = (size_t)B * 129 * sizeof(float);
    cudaFuncSetAttribute(finalize_kernel,
                         cudaFuncAttributeMaxDynamicSharedMemorySize,
                         (int)smemP);
    finalize_kernel<<<M / 8, 256, smemP>>>(F, protos, labels, M, B);

    reduce_kernel<<<1, 1024>>>((float*)d_out, M);
}